// round 1
// baseline (speedup 1.0000x reference)
#include <cuda_runtime.h>

// Problem constants
#define BB   2
#define NN   512
#define DD   256
#define HH   4
#define HDD  64
#define HDH  256   // HH*HDD

// Scratch (device globals; no allocation allowed)
__device__ float g_hq[BB*NN*HDH];
__device__ float g_hk[BB*NN*HDH];
__device__ float g_hv[BB*NN*HDH];
__device__ float g_sq[BB*NN*HH];
__device__ float g_sk[BB*NN*HH];
__device__ float g_aa[HDD];

// ---------------------------------------------------------------------------
// Kernel 1: projections hq = q@Wq+bq, hk = k@Wq+bq, hv = v@Wv+bv
// grid = 96 blocks (3 matrices x 32 row-tiles of 32 rows), 256 threads
// thread computes 8 rows x 4 cols (float4) with x-tile staged in smem
// ---------------------------------------------------------------------------
__global__ __launch_bounds__(256) void proj_kernel(
    const float* __restrict__ q, const float* __restrict__ k, const float* __restrict__ v,
    const float* __restrict__ wq, const float* __restrict__ bq,
    const float* __restrict__ wv, const float* __restrict__ bv)
{
    __shared__ float sh_x[32*256];   // 32KB

    int m  = blockIdx.x >> 5;            // 0=q,1=k,2=v
    int r0 = (blockIdx.x & 31) * 32;
    const float* src  = (m==0) ? q : (m==1) ? k : v;
    const float* W    = (m<2)  ? wq : wv;
    const float* bias = (m<2)  ? bq : bv;
    float* dst        = (m==0) ? g_hq : (m==1) ? g_hk : g_hv;

    // stage 32x256 input tile
    const float4* s4 = (const float4*)src + (size_t)r0*64;
    float4* sh4 = (float4*)sh_x;
    for (int t = threadIdx.x; t < 2048; t += 256) sh4[t] = s4[t];
    __syncthreads();

    int cg = threadIdx.x & 63;   // col group -> cols 4cg..4cg+3
    int rg = threadIdx.x >> 6;   // rows rg*8 .. rg*8+7
    float4 bias4 = ((const float4*)bias)[cg];
    float4 acc[8];
    #pragma unroll
    for (int r = 0; r < 8; r++) acc[r] = bias4;

    const float4* W4 = (const float4*)W;
    #pragma unroll 4
    for (int d = 0; d < 256; d++) {
        float4 w4 = W4[d*64 + cg];
        #pragma unroll
        for (int r = 0; r < 8; r++) {
            float xv = sh_x[(rg*8 + r)*256 + d];
            acc[r].x = fmaf(xv, w4.x, acc[r].x);
            acc[r].y = fmaf(xv, w4.y, acc[r].y);
            acc[r].z = fmaf(xv, w4.z, acc[r].z);
            acc[r].w = fmaf(xv, w4.w, acc[r].w);
        }
    }
    float4* dst4 = (float4*)dst;
    #pragma unroll
    for (int r = 0; r < 8; r++)
        dst4[(size_t)(r0 + rg*8 + r)*64 + cg] = acc[r];
}

// ---------------------------------------------------------------------------
// Kernel 2: per-row base scalars  sq[n,h] = 0.6 * sum_f a[f]*hq[n,h,f]
//           (and sk from hk), plus g_aa = 0.4*a
// grid = 2048 blocks x 128 threads (warp per head)
// ---------------------------------------------------------------------------
__global__ __launch_bounds__(128) void base_kernel(const float* __restrict__ a)
{
    int bid = blockIdx.x;
    if (bid == 0 && threadIdx.x < HDD) g_aa[threadIdx.x] = 0.4f * a[threadIdx.x];

    int m = bid >> 10;          // 0: hq->sq, 1: hk->sk
    int n = bid & 1023;         // b*N + i
    const float* hsrc = m ? g_hk : g_hq;
    float* sdst       = m ? g_sk : g_sq;

    int w = threadIdx.x >> 5, lane = threadIdx.x & 31;
    const float* row = hsrc + (size_t)n*HDH + w*HDD;
    float s = fmaf(a[lane], row[lane], a[lane+32] * row[lane+32]);
    #pragma unroll
    for (int o = 16; o; o >>= 1) s += __shfl_xor_sync(0xffffffffu, s, o);
    if (lane == 0) sdst[n*HH + w] = 0.6f * s;
}

// ---------------------------------------------------------------------------
// Kernel 3: main GAT — one block per (b, h, 32-row i-tile). 512 threads.
//   phase A: logits e[i,j] = sk[i] + sq[j] + sum_f aa[f]*|hq[j,f]+hk[i,f]|
//   phase B: row softmax in smem
//   phase C: write e; AV contraction + ReLU -> h_prime
// ---------------------------------------------------------------------------
__global__ __launch_bounds__(512) void gat_main(float* __restrict__ out_h,
                                                float* __restrict__ out_e)
{
    extern __shared__ float sm[];
    float* sh_e  = sm;                       // 32 * 513
    float* sh_hq = sm + 32*513;              // 64 * 64
    float* sh_sq = sh_hq + 64*64;            // 64
    float* sh_hk = sh_sq + 64;               // 32 * 68 (padded)

    int bid = blockIdx.x;
    int b   = bid >> 6;
    int h   = (bid >> 4) & 3;
    int i0  = (bid & 15) * 32;
    int tid = threadIdx.x;

    // stage hk tile [32 x 64] (padded row stride 68 -> conflict-free LDS.128)
    {
        int il = tid >> 4, fg = tid & 15;
        float4 kv = ((const float4*)(g_hk + (size_t)(b*NN + i0 + il)*HDH + h*HDD))[fg];
        float* dp = sh_hk + il*68 + fg*4;
        dp[0] = kv.x; dp[1] = kv.y; dp[2] = kv.z; dp[3] = kv.w;
    }

    // aa weights in registers (64 floats)
    float4 aar[16];
    #pragma unroll
    for (int g = 0; g < 16; g++) aar[g] = ((const float4*)g_aa)[g];

    int il = tid & 31;          // i lane
    int jl = tid >> 5;          // j lane 0..15
    float sk_i = g_sk[(b*NN + i0 + il)*HH + h];

    // ---- phase A: logits, hq streamed in 64-row stages ----
    for (int js = 0; js < NN; js += 64) {
        __syncthreads();
        for (int t = tid; t < 1024; t += 512) {
            int jr = t >> 4, fg = t & 15;
            ((float4*)(sh_hq + jr*64))[fg] =
                ((const float4*)(g_hq + (size_t)(b*NN + js + jr)*HDH + h*HDD))[fg];
        }
        if (tid < 64) sh_sq[tid] = g_sq[(b*NN + js + tid)*HH + h];
        __syncthreads();

        for (int jj = jl; jj < 64; jj += 16) {
            const float4* qrow = (const float4*)(sh_hq + jj*64);
            const float4* krow = (const float4*)(sh_hk + il*68);
            float ac0 = 0.f, ac1 = 0.f, ac2 = 0.f, ac3 = 0.f;
            #pragma unroll
            for (int g = 0; g < 16; g += 4) {
                {
                    float4 q0 = qrow[g+0], k0 = krow[g+0], aw = aar[g+0];
                    ac0 = fmaf(aw.x, fabsf(q0.x + k0.x), ac0);
                    ac0 = fmaf(aw.y, fabsf(q0.y + k0.y), ac0);
                    ac0 = fmaf(aw.z, fabsf(q0.z + k0.z), ac0);
                    ac0 = fmaf(aw.w, fabsf(q0.w + k0.w), ac0);
                }
                {
                    float4 q0 = qrow[g+1], k0 = krow[g+1], aw = aar[g+1];
                    ac1 = fmaf(aw.x, fabsf(q0.x + k0.x), ac1);
                    ac1 = fmaf(aw.y, fabsf(q0.y + k0.y), ac1);
                    ac1 = fmaf(aw.z, fabsf(q0.z + k0.z), ac1);
                    ac1 = fmaf(aw.w, fabsf(q0.w + k0.w), ac1);
                }
                {
                    float4 q0 = qrow[g+2], k0 = krow[g+2], aw = aar[g+2];
                    ac2 = fmaf(aw.x, fabsf(q0.x + k0.x), ac2);
                    ac2 = fmaf(aw.y, fabsf(q0.y + k0.y), ac2);
                    ac2 = fmaf(aw.z, fabsf(q0.z + k0.z), ac2);
                    ac2 = fmaf(aw.w, fabsf(q0.w + k0.w), ac2);
                }
                {
                    float4 q0 = qrow[g+3], k0 = krow[g+3], aw = aar[g+3];
                    ac3 = fmaf(aw.x, fabsf(q0.x + k0.x), ac3);
                    ac3 = fmaf(aw.y, fabsf(q0.y + k0.y), ac3);
                    ac3 = fmaf(aw.z, fabsf(q0.z + k0.z), ac3);
                    ac3 = fmaf(aw.w, fabsf(q0.w + k0.w), ac3);
                }
            }
            sh_e[il*513 + js + jj] = (ac0 + ac1) + (ac2 + ac3) + sk_i + sh_sq[jj];
        }
    }
    __syncthreads();

    // ---- phase B: row softmax (warp w handles rows 2w, 2w+1) ----
    {
        int w = tid >> 5, lane = tid & 31;
        #pragma unroll
        for (int rr = 0; rr < 2; rr++) {
            float* row = sh_e + (2*w + rr)*513;
            float mx = -1e30f;
            for (int j = lane; j < NN; j += 32) mx = fmaxf(mx, row[j]);
            #pragma unroll
            for (int o = 16; o; o >>= 1) mx = fmaxf(mx, __shfl_xor_sync(0xffffffffu, mx, o));
            float s = 0.f;
            for (int j = lane; j < NN; j += 32) {
                float ex = __expf(row[j] - mx);
                row[j] = ex;
                s += ex;
            }
            #pragma unroll
            for (int o = 16; o; o >>= 1) s += __shfl_xor_sync(0xffffffffu, s, o);
            float inv = 1.f / s;
            for (int j = lane; j < NN; j += 32) row[j] *= inv;
        }
    }
    __syncthreads();

    // ---- phase C1: write e [B,N,N,H] ----
    {
        float* ebase = out_e + ((size_t)(b*NN + i0) * NN) * HH + h;
        for (int t = tid; t < 32*512; t += 512) {
            int i = t >> 9, j = t & 511;
            ebase[(size_t)(i*NN + j) * HH] = sh_e[i*513 + j];
        }
    }

    // ---- phase C2: AV contraction + ReLU ----
    {
        int i2 = tid >> 4, fg = tid & 15;
        const float4* hv4 = (const float4*)(g_hv + (size_t)(b*NN)*HDH + h*HDD) + fg;
        const float* erow = sh_e + i2*513;
        float4 acc = make_float4(0.f, 0.f, 0.f, 0.f);
        #pragma unroll 4
        for (int j = 0; j < NN; j++) {
            float ev = erow[j];
            float4 vv = hv4[(size_t)j*64];
            acc.x = fmaf(ev, vv.x, acc.x);
            acc.y = fmaf(ev, vv.y, acc.y);
            acc.z = fmaf(ev, vv.z, acc.z);
            acc.w = fmaf(ev, vv.w, acc.w);
        }
        acc.x = fmaxf(acc.x, 0.f); acc.y = fmaxf(acc.y, 0.f);
        acc.z = fmaxf(acc.z, 0.f); acc.w = fmaxf(acc.w, 0.f);
        ((float4*)(out_h + (size_t)(b*NN + i0 + i2)*HDH + h*HDD))[fg] = acc;
    }
}

// ---------------------------------------------------------------------------
extern "C" void kernel_launch(void* const* d_in, const int* in_sizes, int n_in,
                              void* d_out, int out_size)
{
    const float* q  = (const float*)d_in[0];
    const float* k  = (const float*)d_in[1];
    const float* v  = (const float*)d_in[2];
    const float* wq = (const float*)d_in[3];
    const float* bq = (const float*)d_in[4];
    const float* wv = (const float*)d_in[5];
    const float* bv = (const float*)d_in[6];
    const float* a  = (const float*)d_in[7];

    float* out_h = (float*)d_out;                      // [B,N,H*HD] = 262144
    float* out_e = out_h + (size_t)BB*NN*HDH;          // [B,N,N,H]  = 2097152

    const int smem_main = (32*513 + 64*64 + 64 + 32*68) * (int)sizeof(float); // 91008 B
    cudaFuncSetAttribute(gat_main, cudaFuncAttributeMaxDynamicSharedMemorySize, smem_main);

    proj_kernel<<<96, 256>>>(q, k, v, wq, bq, wv, bv);
    base_kernel<<<2048, 128>>>(a);
    gat_main<<<128, 512, smem_main>>>(out_h, out_e);
}

// round 3
// speedup vs baseline: 1.1710x; 1.1710x over previous
#include <cuda_runtime.h>

// Problem constants
#define BB   2
#define NN   512
#define DD   256
#define HH   4
#define HDD  64
#define HDH  256   // HH*HDD

// Scratch (device globals; no allocation allowed)
__device__ float g_hq[BB*NN*HDH];
__device__ float g_hk[BB*NN*HDH];
__device__ float g_hv[BB*NN*HDH];
__device__ float g_sq[BB*NN*HH];
__device__ float g_sk[BB*NN*HH];
__device__ float g_aa[HDD];

// ---------------------------------------------------------------------------
// Kernel 1: projections hq = q@Wq+bq, hk = k@Wq+bq, hv = v@Wv+bv
// Block tile: 32 rows x 128 cols. grid = 3 x 32 x 2 = 192 blocks, 256 threads.
// k-chunk 16, X (transposed, stride 36 floats = 144B, float4-aligned) and W
// staged in smem, double-buffered with register prefetch. Thread tile 4x4.
// ---------------------------------------------------------------------------
__global__ __launch_bounds__(256) void proj_kernel(
    const float* __restrict__ q, const float* __restrict__ k, const float* __restrict__ v,
    const float* __restrict__ wq, const float* __restrict__ bq,
    const float* __restrict__ wv, const float* __restrict__ bv)
{
    __shared__ float sx[2][16][36];    // [buf][k][row] padded to 144B rows (16B-aligned)
    __shared__ float sw[2][16][128];   // [buf][k][col]

    int bid = blockIdx.x;
    int m  = bid >> 6;             // 0=q,1=k,2=v
    int rt = (bid >> 1) & 31;      // 32 row tiles
    int ct = bid & 1;              // 2 col tiles
    int r0 = rt * 32, c0 = ct * 128;

    const float* src  = (m==0) ? q : (m==1) ? k : v;
    const float* W    = (m<2)  ? wq : wv;
    const float* bias = (m<2)  ? bq : bv;
    float* dst        = (m==0) ? g_hq : (m==1) ? g_hk : g_hv;

    int tid = threadIdx.x;
    int ry  = tid >> 5;    // 0..7 -> rows ry*4 .. ry*4+3
    int cx  = tid & 31;    // cols cx*4 .. cx*4+3

    float4 b4 = *(const float4*)&bias[c0 + cx*4];
    float4 acc0 = b4, acc1 = b4, acc2 = b4, acc3 = b4;

    // x-load mapping (threads 0..127): row = t>>2 (0..31), dg = t&3 (k-groups of 4)
    int xrow = tid >> 2, xdg = tid & 3;
    // w-load mapping: 2 float4 per thread
    int wd0 = tid >> 5,          wc0 = tid & 31;          // idx = tid
    int wd1 = (tid + 256) >> 5,  wc1 = tid & 31;          // idx = tid+256

    // prefetch chunk 0
    float4 xr = make_float4(0.f,0.f,0.f,0.f);
    if (tid < 128) xr = *(const float4*)&src[(size_t)(r0 + xrow)*DD + xdg*4];
    float4 wr0 = *(const float4*)&W[(size_t)wd0*DD + c0 + wc0*4];
    float4 wr1 = *(const float4*)&W[(size_t)wd1*DD + c0 + wc1*4];

    if (tid < 128) {
        sx[0][xdg*4+0][xrow] = xr.x;
        sx[0][xdg*4+1][xrow] = xr.y;
        sx[0][xdg*4+2][xrow] = xr.z;
        sx[0][xdg*4+3][xrow] = xr.w;
    }
    *(float4*)&sw[0][wd0][wc0*4] = wr0;
    *(float4*)&sw[0][wd1][wc1*4] = wr1;
    __syncthreads();

    #pragma unroll 1
    for (int c = 0; c < 16; c++) {
        int buf = c & 1;
        // prefetch next chunk into registers (hides L2 latency behind compute)
        if (c < 15) {
            int dbase = (c + 1) * 16;
            if (tid < 128) xr = *(const float4*)&src[(size_t)(r0 + xrow)*DD + dbase + xdg*4];
            wr0 = *(const float4*)&W[(size_t)(dbase + wd0)*DD + c0 + wc0*4];
            wr1 = *(const float4*)&W[(size_t)(dbase + wd1)*DD + c0 + wc1*4];
        }

        // compute this chunk from smem
        #pragma unroll
        for (int kk = 0; kk < 16; kk++) {
            float4 xv = *(const float4*)&sx[buf][kk][ry*4];   // broadcast within warp
            float4 wv = *(const float4*)&sw[buf][kk][cx*4];
            acc0.x = fmaf(xv.x, wv.x, acc0.x);
            acc0.y = fmaf(xv.x, wv.y, acc0.y);
            acc0.z = fmaf(xv.x, wv.z, acc0.z);
            acc0.w = fmaf(xv.x, wv.w, acc0.w);
            acc1.x = fmaf(xv.y, wv.x, acc1.x);
            acc1.y = fmaf(xv.y, wv.y, acc1.y);
            acc1.z = fmaf(xv.y, wv.z, acc1.z);
            acc1.w = fmaf(xv.y, wv.w, acc1.w);
            acc2.x = fmaf(xv.z, wv.x, acc2.x);
            acc2.y = fmaf(xv.z, wv.y, acc2.y);
            acc2.z = fmaf(xv.z, wv.z, acc2.z);
            acc2.w = fmaf(xv.z, wv.w, acc2.w);
            acc3.x = fmaf(xv.w, wv.x, acc3.x);
            acc3.y = fmaf(xv.w, wv.y, acc3.y);
            acc3.z = fmaf(xv.w, wv.z, acc3.z);
            acc3.w = fmaf(xv.w, wv.w, acc3.w);
        }

        if (c < 15) {
            int nbuf = buf ^ 1;
            if (tid < 128) {
                sx[nbuf][xdg*4+0][xrow] = xr.x;
                sx[nbuf][xdg*4+1][xrow] = xr.y;
                sx[nbuf][xdg*4+2][xrow] = xr.z;
                sx[nbuf][xdg*4+3][xrow] = xr.w;
            }
            *(float4*)&sw[nbuf][wd0][wc0*4] = wr0;
            *(float4*)&sw[nbuf][wd1][wc1*4] = wr1;
        }
        __syncthreads();
    }

    float4* dst4 = (float4*)dst;
    size_t obase = (size_t)(r0 + ry*4) * 64 + (c0 >> 2) + cx;
    dst4[obase + 0*64] = acc0;
    dst4[obase + 1*64] = acc1;
    dst4[obase + 2*64] = acc2;
    dst4[obase + 3*64] = acc3;
}

// ---------------------------------------------------------------------------
// Kernel 2: per-row base scalars  sq[n,h] = 0.6 * sum_f a[f]*hq[n,h,f]
//           (and sk from hk), plus g_aa = 0.4*a
// ---------------------------------------------------------------------------
__global__ __launch_bounds__(128) void base_kernel(const float* __restrict__ a)
{
    int bid = blockIdx.x;
    if (bid == 0 && threadIdx.x < HDD) g_aa[threadIdx.x] = 0.4f * a[threadIdx.x];

    int m = bid >> 10;          // 0: hq->sq, 1: hk->sk
    int n = bid & 1023;         // b*N + i
    const float* hsrc = m ? g_hk : g_hq;
    float* sdst       = m ? g_sk : g_sq;

    int w = threadIdx.x >> 5, lane = threadIdx.x & 31;
    const float* row = hsrc + (size_t)n*HDH + w*HDD;
    float s = fmaf(a[lane], row[lane], a[lane+32] * row[lane+32]);
    #pragma unroll
    for (int o = 16; o; o >>= 1) s += __shfl_xor_sync(0xffffffffu, s, o);
    if (lane == 0) sdst[n*HH + w] = 0.6f * s;
}

// ---------------------------------------------------------------------------
// Kernel 3: main GAT — one block per (b, h, 32-row i-tile). 512 threads.
//   phase A: logits e[i,j] = sk[i] + sq[j] + sum_f aa[f]*|hq[j,f]+hk[i,f]|
//   phase B: row softmax in smem
//   phase C: write e; AV contraction + ReLU -> h_prime
// ---------------------------------------------------------------------------
__global__ __launch_bounds__(512) void gat_main(float* __restrict__ out_h,
                                                float* __restrict__ out_e)
{
    extern __shared__ float sm[];
    float* sh_e  = sm;                       // 32 * 513
    float* sh_hq = sm + 32*513;              // 64 * 64
    float* sh_sq = sh_hq + 64*64;            // 64
    float* sh_hk = sh_sq + 64;               // 32 * 68 (padded)

    int bid = blockIdx.x;
    int b   = bid >> 6;
    int h   = (bid >> 4) & 3;
    int i0  = (bid & 15) * 32;
    int tid = threadIdx.x;

    // stage hk tile [32 x 64] (padded row stride 68 -> conflict-free LDS.128)
    {
        int il = tid >> 4, fg = tid & 15;
        float4 kv = ((const float4*)(g_hk + (size_t)(b*NN + i0 + il)*HDH + h*HDD))[fg];
        float* dp = sh_hk + il*68 + fg*4;
        dp[0] = kv.x; dp[1] = kv.y; dp[2] = kv.z; dp[3] = kv.w;
    }

    // aa weights in registers (64 floats)
    float4 aar[16];
    #pragma unroll
    for (int g = 0; g < 16; g++) aar[g] = ((const float4*)g_aa)[g];

    int il = tid & 31;          // i lane
    int jl = tid >> 5;          // j lane 0..15
    float sk_i = g_sk[(b*NN + i0 + il)*HH + h];

    // ---- phase A: logits, hq streamed in 64-row stages ----
    for (int js = 0; js < NN; js += 64) {
        __syncthreads();
        for (int t = tid; t < 1024; t += 512) {
            int jr = t >> 4, fg = t & 15;
            ((float4*)(sh_hq + jr*64))[fg] =
                ((const float4*)(g_hq + (size_t)(b*NN + js + jr)*HDH + h*HDD))[fg];
        }
        if (tid < 64) sh_sq[tid] = g_sq[(b*NN + js + tid)*HH + h];
        __syncthreads();

        for (int jj = jl; jj < 64; jj += 16) {
            const float4* qrow = (const float4*)(sh_hq + jj*64);
            const float4* krow = (const float4*)(sh_hk + il*68);
            float ac0 = 0.f, ac1 = 0.f, ac2 = 0.f, ac3 = 0.f;
            #pragma unroll
            for (int g = 0; g < 16; g += 4) {
                {
                    float4 q0 = qrow[g+0], k0 = krow[g+0], aw = aar[g+0];
                    ac0 = fmaf(aw.x, fabsf(q0.x + k0.x), ac0);
                    ac0 = fmaf(aw.y, fabsf(q0.y + k0.y), ac0);
                    ac0 = fmaf(aw.z, fabsf(q0.z + k0.z), ac0);
                    ac0 = fmaf(aw.w, fabsf(q0.w + k0.w), ac0);
                }
                {
                    float4 q0 = qrow[g+1], k0 = krow[g+1], aw = aar[g+1];
                    ac1 = fmaf(aw.x, fabsf(q0.x + k0.x), ac1);
                    ac1 = fmaf(aw.y, fabsf(q0.y + k0.y), ac1);
                    ac1 = fmaf(aw.z, fabsf(q0.z + k0.z), ac1);
                    ac1 = fmaf(aw.w, fabsf(q0.w + k0.w), ac1);
                }
                {
                    float4 q0 = qrow[g+2], k0 = krow[g+2], aw = aar[g+2];
                    ac2 = fmaf(aw.x, fabsf(q0.x + k0.x), ac2);
                    ac2 = fmaf(aw.y, fabsf(q0.y + k0.y), ac2);
                    ac2 = fmaf(aw.z, fabsf(q0.z + k0.z), ac2);
                    ac2 = fmaf(aw.w, fabsf(q0.w + k0.w), ac2);
                }
                {
                    float4 q0 = qrow[g+3], k0 = krow[g+3], aw = aar[g+3];
                    ac3 = fmaf(aw.x, fabsf(q0.x + k0.x), ac3);
                    ac3 = fmaf(aw.y, fabsf(q0.y + k0.y), ac3);
                    ac3 = fmaf(aw.z, fabsf(q0.z + k0.z), ac3);
                    ac3 = fmaf(aw.w, fabsf(q0.w + k0.w), ac3);
                }
            }
            sh_e[il*513 + js + jj] = (ac0 + ac1) + (ac2 + ac3) + sk_i + sh_sq[jj];
        }
    }
    __syncthreads();

    // ---- phase B: row softmax (warp w handles rows 2w, 2w+1) ----
    {
        int w = tid >> 5, lane = tid & 31;
        #pragma unroll
        for (int rr = 0; rr < 2; rr++) {
            float* row = sh_e + (2*w + rr)*513;
            float mx = -1e30f;
            for (int j = lane; j < NN; j += 32) mx = fmaxf(mx, row[j]);
            #pragma unroll
            for (int o = 16; o; o >>= 1) mx = fmaxf(mx, __shfl_xor_sync(0xffffffffu, mx, o));
            float s = 0.f;
            for (int j = lane; j < NN; j += 32) {
                float ex = __expf(row[j] - mx);
                row[j] = ex;
                s += ex;
            }
            #pragma unroll
            for (int o = 16; o; o >>= 1) s += __shfl_xor_sync(0xffffffffu, s, o);
            float inv = 1.f / s;
            for (int j = lane; j < NN; j += 32) row[j] *= inv;
        }
    }
    __syncthreads();

    // ---- phase C1: write e [B,N,N,H] ----
    {
        float* ebase = out_e + ((size_t)(b*NN + i0) * NN) * HH + h;
        for (int t = tid; t < 32*512; t += 512) {
            int i = t >> 9, j = t & 511;
            ebase[(size_t)(i*NN + j) * HH] = sh_e[i*513 + j];
        }
    }

    // ---- phase C2: AV contraction + ReLU ----
    {
        int i2 = tid >> 4, fg = tid & 15;
        const float4* hv4 = (const float4*)(g_hv + (size_t)(b*NN)*HDH + h*HDD) + fg;
        const float* erow = sh_e + i2*513;
        float4 acc = make_float4(0.f, 0.f, 0.f, 0.f);
        #pragma unroll 4
        for (int j = 0; j < NN; j++) {
            float ev = erow[j];
            float4 vv = hv4[(size_t)j*64];
            acc.x = fmaf(ev, vv.x, acc.x);
            acc.y = fmaf(ev, vv.y, acc.y);
            acc.z = fmaf(ev, vv.z, acc.z);
            acc.w = fmaf(ev, vv.w, acc.w);
        }
        acc.x = fmaxf(acc.x, 0.f); acc.y = fmaxf(acc.y, 0.f);
        acc.z = fmaxf(acc.z, 0.f); acc.w = fmaxf(acc.w, 0.f);
        ((float4*)(out_h + (size_t)(b*NN + i0 + i2)*HDH + h*HDD))[fg] = acc;
    }
}

// ---------------------------------------------------------------------------
extern "C" void kernel_launch(void* const* d_in, const int* in_sizes, int n_in,
                              void* d_out, int out_size)
{
    const float* q  = (const float*)d_in[0];
    const float* k  = (const float*)d_in[1];
    const float* v  = (const float*)d_in[2];
    const float* wq = (const float*)d_in[3];
    const float* bq = (const float*)d_in[4];
    const float* wv = (const float*)d_in[5];
    const float* bv = (const float*)d_in[6];
    const float* a  = (const float*)d_in[7];

    float* out_h = (float*)d_out;                      // [B,N,H*HD] = 262144
    float* out_e = out_h + (size_t)BB*NN*HDH;          // [B,N,N,H]  = 2097152

    const int smem_main = (32*513 + 64*64 + 64 + 32*68) * (int)sizeof(float); // 91008 B
    cudaFuncSetAttribute(gat_main, cudaFuncAttributeMaxDynamicSharedMemorySize, smem_main);

    proj_kernel<<<192, 256>>>(q, k, v, wq, bq, wv, bv);
    base_kernel<<<2048, 128>>>(a);
    gat_main<<<128, 512, smem_main>>>(out_h, out_e);
}

// round 4
// speedup vs baseline: 1.6722x; 1.4280x over previous
#include <cuda_runtime.h>

// Problem constants
#define BB   2
#define NN   512
#define DD   256
#define HH   4
#define HDD  64
#define HDH  256   // HH*HDD

typedef unsigned long long ull;
#define ABS2 0x7fffffff7fffffffULL

// Scratch (device globals; no allocation allowed)
__device__ __align__(16) float g_hq[BB*NN*HDH];
__device__ __align__(16) float g_hk[BB*NN*HDH];
__device__ __align__(16) float g_hv[BB*NN*HDH];
__device__ __align__(16) float g_sq[BB*NN*HH];
__device__ __align__(16) float g_sk[BB*NN*HH];
__device__ __align__(16) float g_aa[HDD];

// ---- packed f32x2 helpers (sm_103a) ----
__device__ __forceinline__ ull add2(ull a, ull b) {
    ull r; asm("add.rn.f32x2 %0, %1, %2;" : "=l"(r) : "l"(a), "l"(b)); return r;
}
__device__ __forceinline__ ull fma2(ull a, ull b, ull c) {
    ull r; asm("fma.rn.f32x2 %0, %1, %2, %3;" : "=l"(r) : "l"(a), "l"(b), "l"(c)); return r;
}
__device__ __forceinline__ ull pack2(float lo, float hi) {
    ull r; asm("mov.b64 %0, {%1, %2};" : "=l"(r) : "f"(lo), "f"(hi)); return r;
}
__device__ __forceinline__ float2 unpack2(ull v) {
    float2 f; asm("mov.b64 {%0, %1}, %2;" : "=f"(f.x), "=f"(f.y) : "l"(v)); return f;
}

// ---------------------------------------------------------------------------
// Kernel 1: projections hq = q@Wq+bq, hk = k@Wq+bq, hv = v@Wv+bv
// (unchanged from round 3 — 22.9us measured)
// ---------------------------------------------------------------------------
__global__ __launch_bounds__(256) void proj_kernel(
    const float* __restrict__ q, const float* __restrict__ k, const float* __restrict__ v,
    const float* __restrict__ wq, const float* __restrict__ bq,
    const float* __restrict__ wv, const float* __restrict__ bv)
{
    __shared__ float sx[2][16][36];    // [buf][k][row] padded to 144B rows (16B-aligned)
    __shared__ float sw[2][16][128];   // [buf][k][col]

    int bid = blockIdx.x;
    int m  = bid >> 6;             // 0=q,1=k,2=v
    int rt = (bid >> 1) & 31;      // 32 row tiles
    int ct = bid & 1;              // 2 col tiles
    int r0 = rt * 32, c0 = ct * 128;

    const float* src  = (m==0) ? q : (m==1) ? k : v;
    const float* W    = (m<2)  ? wq : wv;
    const float* bias = (m<2)  ? bq : bv;
    float* dst        = (m==0) ? g_hq : (m==1) ? g_hk : g_hv;

    int tid = threadIdx.x;
    int ry  = tid >> 5;    // 0..7 -> rows ry*4 .. ry*4+3
    int cx  = tid & 31;    // cols cx*4 .. cx*4+3

    float4 b4 = *(const float4*)&bias[c0 + cx*4];
    float4 acc0 = b4, acc1 = b4, acc2 = b4, acc3 = b4;

    int xrow = tid >> 2, xdg = tid & 3;
    int wd0 = tid >> 5,          wc0 = tid & 31;
    int wd1 = (tid + 256) >> 5,  wc1 = tid & 31;

    float4 xr = make_float4(0.f,0.f,0.f,0.f);
    if (tid < 128) xr = *(const float4*)&src[(size_t)(r0 + xrow)*DD + xdg*4];
    float4 wr0 = *(const float4*)&W[(size_t)wd0*DD + c0 + wc0*4];
    float4 wr1 = *(const float4*)&W[(size_t)wd1*DD + c0 + wc1*4];

    if (tid < 128) {
        sx[0][xdg*4+0][xrow] = xr.x;
        sx[0][xdg*4+1][xrow] = xr.y;
        sx[0][xdg*4+2][xrow] = xr.z;
        sx[0][xdg*4+3][xrow] = xr.w;
    }
    *(float4*)&sw[0][wd0][wc0*4] = wr0;
    *(float4*)&sw[0][wd1][wc1*4] = wr1;
    __syncthreads();

    #pragma unroll 1
    for (int c = 0; c < 16; c++) {
        int buf = c & 1;
        if (c < 15) {
            int dbase = (c + 1) * 16;
            if (tid < 128) xr = *(const float4*)&src[(size_t)(r0 + xrow)*DD + dbase + xdg*4];
            wr0 = *(const float4*)&W[(size_t)(dbase + wd0)*DD + c0 + wc0*4];
            wr1 = *(const float4*)&W[(size_t)(dbase + wd1)*DD + c0 + wc1*4];
        }

        #pragma unroll
        for (int kk = 0; kk < 16; kk++) {
            float4 xv = *(const float4*)&sx[buf][kk][ry*4];
            float4 wv = *(const float4*)&sw[buf][kk][cx*4];
            acc0.x = fmaf(xv.x, wv.x, acc0.x);
            acc0.y = fmaf(xv.x, wv.y, acc0.y);
            acc0.z = fmaf(xv.x, wv.z, acc0.z);
            acc0.w = fmaf(xv.x, wv.w, acc0.w);
            acc1.x = fmaf(xv.y, wv.x, acc1.x);
            acc1.y = fmaf(xv.y, wv.y, acc1.y);
            acc1.z = fmaf(xv.y, wv.z, acc1.z);
            acc1.w = fmaf(xv.y, wv.w, acc1.w);
            acc2.x = fmaf(xv.z, wv.x, acc2.x);
            acc2.y = fmaf(xv.z, wv.y, acc2.y);
            acc2.z = fmaf(xv.z, wv.z, acc2.z);
            acc2.w = fmaf(xv.z, wv.w, acc2.w);
            acc3.x = fmaf(xv.w, wv.x, acc3.x);
            acc3.y = fmaf(xv.w, wv.y, acc3.y);
            acc3.z = fmaf(xv.w, wv.z, acc3.z);
            acc3.w = fmaf(xv.w, wv.w, acc3.w);
        }

        if (c < 15) {
            int nbuf = buf ^ 1;
            if (tid < 128) {
                sx[nbuf][xdg*4+0][xrow] = xr.x;
                sx[nbuf][xdg*4+1][xrow] = xr.y;
                sx[nbuf][xdg*4+2][xrow] = xr.z;
                sx[nbuf][xdg*4+3][xrow] = xr.w;
            }
            *(float4*)&sw[nbuf][wd0][wc0*4] = wr0;
            *(float4*)&sw[nbuf][wd1][wc1*4] = wr1;
        }
        __syncthreads();
    }

    float4* dst4 = (float4*)dst;
    size_t obase = (size_t)(r0 + ry*4) * 64 + (c0 >> 2) + cx;
    dst4[obase + 0*64] = acc0;
    dst4[obase + 1*64] = acc1;
    dst4[obase + 2*64] = acc2;
    dst4[obase + 3*64] = acc3;
}

// ---------------------------------------------------------------------------
// Kernel 2: per-row base scalars  sq[n,h] = 0.6 * sum_f a[f]*hq[n,h,f]
//           (and sk from hk), plus g_aa = 0.4*a
// ---------------------------------------------------------------------------
__global__ __launch_bounds__(128) void base_kernel(const float* __restrict__ a)
{
    int bid = blockIdx.x;
    if (bid == 0 && threadIdx.x < HDD) g_aa[threadIdx.x] = 0.4f * a[threadIdx.x];

    int m = bid >> 10;          // 0: hq->sq, 1: hk->sk
    int n = bid & 1023;         // b*N + i
    const float* hsrc = m ? g_hk : g_hq;
    float* sdst       = m ? g_sk : g_sq;

    int w = threadIdx.x >> 5, lane = threadIdx.x & 31;
    const float* row = hsrc + (size_t)n*HDH + w*HDD;
    float s = fmaf(a[lane], row[lane], a[lane+32] * row[lane+32]);
    #pragma unroll
    for (int o = 16; o; o >>= 1) s += __shfl_xor_sync(0xffffffffu, s, o);
    if (lane == 0) sdst[n*HH + w] = 0.6f * s;
}

// ---------------------------------------------------------------------------
// Kernel 3: main GAT — one block per (b, h, 32-row i-tile). 256 threads.
// krow + aa weights register-resident; full hq tile in smem; packed f32x2.
// smem layout (bytes):
//   sh_hq : 512*64 floats  = 131072   (reused for hv in phase C)
//   sh_e  : 32*513 floats  =  65664
//   sh_hk : 32*68  floats  =   8704
//   sh_sq : 512 floats     =   2048
//   total                   = 207488
// ---------------------------------------------------------------------------
__global__ __launch_bounds__(256) void gat_main(float* __restrict__ out_h,
                                                float* __restrict__ out_e)
{
    extern __shared__ float sm[];
    float* sh_hq = sm;                        // 512*64
    float* sh_e  = sh_hq + 512*64;            // 32*513
    float* sh_hk = sh_e + 32*513;             // 32*68
    float* sh_sq = sh_hk + 32*68;             // 512

    int bid = blockIdx.x;
    int b   = bid >> 6;
    int h   = (bid >> 4) & 3;
    int i0  = (bid & 15) * 32;
    int tid = threadIdx.x;
    int lane = tid & 31;
    int wid  = tid >> 5;        // 0..7

    // ---- stage hq tile [512 x 64] (contiguous, accessed via broadcast) ----
    {
        const float4* gq4 = (const float4*)(g_hq + (size_t)b*NN*HDH);
        float4* dq4 = (float4*)sh_hq;
        for (int t = tid; t < 512*16; t += 256) {
            int r = t >> 4, fgi = t & 15;
            dq4[r*16 + fgi] = gq4[(size_t)r*64 + h*16 + fgi];
        }
    }
    // ---- stage hk tile [32 x 64] padded to stride 68 (conflict-free) ----
    {
        int il2 = tid >> 3, fg2 = tid & 7;      // 32 rows x 8 float2-groups? use float4: 32x16 by 256 threads? 512 float4 / 256 = 2 each
    }
    {
        for (int t = tid; t < 32*16; t += 256) {
            int r = t >> 4, fgi = t & 15;
            float4 kv = ((const float4*)(g_hk + (size_t)(b*NN + i0 + r)*HDH + h*HDD))[fgi];
            *(float4*)(sh_hk + r*68 + fgi*4) = kv;
        }
    }
    // ---- stage sq row scalars for this (b,h) ----
    for (int t = tid; t < NN; t += 256)
        sh_sq[t] = g_sq[(b*NN + t)*HH + h];
    __syncthreads();

    // ---- load krow (this lane's i) and aa weights into registers ----
    ull kr[32], aw[32];
    {
        const ulonglong2* krow2 = (const ulonglong2*)(sh_hk + lane*68);
        const ulonglong2* aa2   = (const ulonglong2*)g_aa;
        #pragma unroll
        for (int g = 0; g < 16; g++) {
            ulonglong2 kk = krow2[g];
            kr[2*g]   = kk.x;
            kr[2*g+1] = kk.y;
            ulonglong2 av = aa2[g];
            aw[2*g]   = av.x;
            aw[2*g+1] = av.y;
        }
    }
    float sk_i = g_sk[(b*NN + i0 + lane)*HH + h];

    // ---- phase A: logits. Each warp handles j = wid, wid+8, ... ----
    for (int j = wid; j < NN; j += 8) {
        const ulonglong2* q2 = (const ulonglong2*)(sh_hq + j*64);
        ull acc0 = 0ULL, acc1 = 0ULL;
        #pragma unroll
        for (int g = 0; g < 16; g++) {
            ulonglong2 qq = q2[g];                       // broadcast LDS.128
            ull t0 = add2(qq.x, kr[2*g]) & ABS2;
            acc0 = fma2(aw[2*g], t0, acc0);
            ull t1 = add2(qq.y, kr[2*g+1]) & ABS2;
            acc1 = fma2(aw[2*g+1], t1, acc1);
        }
        float2 a0 = unpack2(acc0), a1 = unpack2(acc1);
        sh_e[lane*513 + j] = (a0.x + a0.y) + (a1.x + a1.y) + sk_i + sh_sq[j];
    }
    __syncthreads();

    // ---- phase B: row softmax (warp w -> rows 4w..4w+3) ----
    {
        #pragma unroll
        for (int rr = 0; rr < 4; rr++) {
            float* row = sh_e + (4*wid + rr)*513;
            float mx = -1e30f;
            for (int j = lane; j < NN; j += 32) mx = fmaxf(mx, row[j]);
            #pragma unroll
            for (int o = 16; o; o >>= 1) mx = fmaxf(mx, __shfl_xor_sync(0xffffffffu, mx, o));
            float s = 0.f;
            for (int j = lane; j < NN; j += 32) {
                float ex = __expf(row[j] - mx);
                row[j] = ex;
                s += ex;
            }
            #pragma unroll
            for (int o = 16; o; o >>= 1) s += __shfl_xor_sync(0xffffffffu, s, o);
            float inv = 1.f / s;
            for (int j = lane; j < NN; j += 32) row[j] *= inv;
        }
    }
    __syncthreads();

    // ---- phase C1: write e [B,N,N,H]; also stage hv into sh_hq ----
    {
        float* ebase = out_e + ((size_t)(b*NN + i0) * NN) * HH + h;
        for (int t = tid; t < 32*512; t += 256) {
            int i = t >> 9, j = t & 511;
            ebase[(size_t)(i*NN + j) * HH] = sh_e[i*513 + j];
        }
        const float4* gv4 = (const float4*)(g_hv + (size_t)b*NN*HDH);
        float4* dv4 = (float4*)sh_hq;
        for (int t = tid; t < 512*16; t += 256) {
            int r = t >> 4, fgi = t & 15;
            dv4[r*16 + fgi] = gv4[(size_t)r*64 + h*16 + fgi];
        }
    }
    __syncthreads();

    // ---- phase C2: AV contraction + ReLU (packed). Thread -> (2 rows, 1 fg) ----
    {
        int iA = tid >> 4;          // 0..15
        int iB = iA + 16;
        int fg = tid & 15;
        const float* erowA = sh_e + iA*513;
        const float* erowB = sh_e + iB*513;
        const ulonglong2* vbase = (const ulonglong2*)sh_hq + fg;   // stride 16 ull2 per row

        ull a0 = 0ULL, a1 = 0ULL, b0 = 0ULL, b1 = 0ULL;
        #pragma unroll 4
        for (int j = 0; j < NN; j++) {
            ulonglong2 vv = vbase[j*16];
            float evA = erowA[j], evB = erowB[j];
            ull eA = pack2(evA, evA);
            ull eB = pack2(evB, evB);
            a0 = fma2(eA, vv.x, a0);
            a1 = fma2(eA, vv.y, a1);
            b0 = fma2(eB, vv.x, b0);
            b1 = fma2(eB, vv.y, b1);
        }
        float2 a0f = unpack2(a0), a1f = unpack2(a1);
        float2 b0f = unpack2(b0), b1f = unpack2(b1);
        float4 ra = make_float4(fmaxf(a0f.x,0.f), fmaxf(a0f.y,0.f),
                                fmaxf(a1f.x,0.f), fmaxf(a1f.y,0.f));
        float4 rb = make_float4(fmaxf(b0f.x,0.f), fmaxf(b0f.y,0.f),
                                fmaxf(b1f.x,0.f), fmaxf(b1f.y,0.f));
        ((float4*)(out_h + (size_t)(b*NN + i0 + iA)*HDH + h*HDD))[fg] = ra;
        ((float4*)(out_h + (size_t)(b*NN + i0 + iB)*HDH + h*HDD))[fg] = rb;
    }
}

// ---------------------------------------------------------------------------
extern "C" void kernel_launch(void* const* d_in, const int* in_sizes, int n_in,
                              void* d_out, int out_size)
{
    const float* q  = (const float*)d_in[0];
    const float* k  = (const float*)d_in[1];
    const float* v  = (const float*)d_in[2];
    const float* wq = (const float*)d_in[3];
    const float* bq = (const float*)d_in[4];
    const float* wv = (const float*)d_in[5];
    const float* bv = (const float*)d_in[6];
    const float* a  = (const float*)d_in[7];

    float* out_h = (float*)d_out;                      // [B,N,H*HD] = 262144
    float* out_e = out_h + (size_t)BB*NN*HDH;          // [B,N,N,H]  = 2097152

    const int smem_main = (512*64 + 32*513 + 32*68 + 512) * (int)sizeof(float); // 207488 B
    cudaFuncSetAttribute(gat_main, cudaFuncAttributeMaxDynamicSharedMemorySize, smem_main);

    proj_kernel<<<192, 256>>>(q, k, v, wq, bq, wv, bv);
    base_kernel<<<2048, 128>>>(a);
    gat_main<<<128, 256, smem_main>>>(out_h, out_e);
}